// round 14
// baseline (speedup 1.0000x reference)
#include <cuda_runtime.h>
#include <cuda_fp16.h>
#include <cstdint>
#include <math.h>

// ---------------- problem constants ----------------
#define Ncfg 16
#define Ccfg 16
#define Tcfg 300
#define Vcfg 25
#define Dcfg 400           // C*V
#define DH   200           // head dim (H=2)
#define FFc  1600
#define Lw   9
#define Wcfg 291           // T - L
#define NW   (Ncfg*Wcfg)   // 4656 windows
#define M2   (NW*Lw)       // 41904 window rows
#define NT   (Ncfg*Tcfg)   // 4800 tokens
#define WB   3             // windows per attention block (291 = 97*3)
#define TOK  (WB + Lw - 1) // 11 tokens per attention block

typedef __half hf;

// ---------------- scratch (device globals; no allocs allowed) ----------------
__device__ float g_xs   [NT * Dcfg];
__device__ hf    g_xs_f [NT * Dcfg];
__device__ hf    g_win_f[3 * Dcfg * Dcfg];
__device__ hf    g_wout_f[Dcfg * Dcfg];
__device__ hf    g_w1_f [FFc * Dcfg];
__device__ hf    g_w2_f [Dcfg * FFc];
__device__ hf    g_qkv_f[NT * 3 * Dcfg];
__device__ hf    g_attn_f[M2 * Dcfg];
__device__ float g_h1   [M2 * Dcfg];
__device__ hf    g_h1_f [M2 * Dcfg];
__device__ hf    g_ff_f [(size_t)M2 * FFc];
__device__ float g_h2   [M2 * Dcfg];

// ---------------- helpers ----------------
__device__ __forceinline__ uint32_t smem_u32(const void* p) {
    uint32_t a;
    asm("{ .reg .u64 t; cvta.to.shared.u64 t, %1; cvt.u32.u64 %0, t; }" : "=r"(a) : "l"(p));
    return a;
}
#define SWZ128(o) ((o) ^ (((o) >> 3) & 0x70))

__device__ __forceinline__ void ldsm4(uint32_t* r, uint32_t a) {
    asm volatile("ldmatrix.sync.aligned.m8n8.x4.shared.b16 {%0,%1,%2,%3}, [%4];"
        : "=r"(r[0]), "=r"(r[1]), "=r"(r[2]), "=r"(r[3]) : "r"(a));
}
// mma m16n8k16 row.col f32 += f16*f16
__device__ __forceinline__ void mma16816(float* c, const uint32_t* a, const uint32_t* b) {
    asm volatile("mma.sync.aligned.m16n8k16.row.col.f32.f16.f16.f32 "
        "{%0,%1,%2,%3}, {%4,%5,%6,%7}, {%8,%9}, {%0,%1,%2,%3};"
        : "+f"(c[0]), "+f"(c[1]), "+f"(c[2]), "+f"(c[3])
        : "r"(a[0]), "r"(a[1]), "r"(a[2]), "r"(a[3]), "r"(b[0]), "r"(b[1]));
}
#define CP_COMMIT() asm volatile("cp.async.commit_group;" ::: "memory")
#define CP_WAIT1()  asm volatile("cp.async.wait_group 1;" ::: "memory")

__device__ __forceinline__ void store_half4(hf* p, float4 v) {
    __half2* p2 = (__half2*)p;
    p2[0] = __floats2half2_rn(v.x, v.y);
    p2[1] = __floats2half2_rn(v.z, v.w);
}

// ---------------- smem: [A 16K][B 8K] x 2 stages = 48 KB ----------------
#define TILE_A   16384                   // 128 rows x 128B
#define TILE_B   8192                    // 64 rows x 128B
#define BUF_BYTES (TILE_A + TILE_B)      // 24576
#define SMEM_TOTAL (2 * BUF_BYTES)       // 49152

__device__ __forceinline__ void load_planeA(const hf* __restrict__ G, int rowBase,
                                            int rows, int K, int kbase, uint32_t sdst) {
    int t = threadIdx.x;
    int r = t >> 1, half = t & 1;
    int gr = rowBase + r;
    bool rok = gr < rows;
    const hf* gp = G + (size_t)(rok ? gr : 0) * K;
#pragma unroll
    for (int i = 0; i < 4; i++) {
        int kc = kbase + half * 32 + i * 8;
        int boff = r * 128 + half * 64 + i * 16;
        uint32_t dst = sdst + SWZ128(boff);
        int srcsz = (rok && kc + 8 <= K) ? 16 : 0;
        asm volatile("cp.async.cg.shared.global [%0], [%1], 16, %2;"
                     :: "r"(dst), "l"(gp + kc), "r"(srcsz));
    }
}
__device__ __forceinline__ void load_planeB(const hf* __restrict__ G, int rowBase,
                                            int rows, int K, int kbase, uint32_t sdst) {
    int t = threadIdx.x;
    int r = t >> 2, q = t & 3;
    int gr = rowBase + r;
    bool rok = gr < rows;
    const hf* gp = G + (size_t)(rok ? gr : 0) * K;
#pragma unroll
    for (int i = 0; i < 2; i++) {
        int g8 = q + i * 4;
        int kc = kbase + g8 * 8;
        int boff = r * 128 + g8 * 16;
        uint32_t dst = sdst + SWZ128(boff);
        int srcsz = (rok && kc + 8 <= K) ? 16 : 0;
        asm volatile("cp.async.cg.shared.global [%0], [%1], 16, %2;"
                     :: "r"(dst), "l"(gp + kc), "r"(srcsz));
    }
}

// ---------------- HMMA GEMM: C[M,Nn] = A[M,K] @ B[Nn,K]^T + bias, epilogues --------
// EPI: 0 bias->fp32 | 1 bias+gelu->fp16 | 2 bias+res(gathered xs)->fp32
//      3 bias+res(row)->fp32 | 4 bias->fp16
template <int EPI>
__global__ void __launch_bounds__(256, 3) k_mma(
    const hf* __restrict__ A, const hf* __restrict__ B,
    const float* __restrict__ bias, const float* __restrict__ res,
    float* __restrict__ Cf, hf* __restrict__ Ch,
    int M, int Nn, int K)
{
    extern __shared__ char smem[];
    uint32_t sbase = smem_u32(smem);
    int tid = threadIdx.x;
    int wid = tid >> 5, lane = tid & 31;
    int wm = wid >> 1, wn = wid & 1;          // warp grid 4(m) x 2(n); tile 32x32
    int rowBase = blockIdx.y * 128;
    int colBase = blockIdx.x * 64;

    float acc[2][4][4];
#pragma unroll
    for (int a = 0; a < 2; a++)
#pragma unroll
        for (int b = 0; b < 4; b++)
#pragma unroll
            for (int c = 0; c < 4; c++) acc[a][b][c] = 0.f;

    int nChunks = (K + 63) / 64;

    auto issue = [&](int c, int s) {
        uint32_t sb = sbase + s * BUF_BYTES;
        int kb = c * 64;
        load_planeA(A, rowBase, M,  K, kb, sb);
        load_planeB(B, colBase, Nn, K, kb, sb + TILE_A);
    };

    issue(0, 0);
    CP_COMMIT();
    if (nChunks > 1) issue(1, 1);
    CP_COMMIT();

    int aRow = wm * 32 + (lane & 15);
    int aKb  = (lane >> 4) << 4;
    int bRowP = wn * 32 + ((lane >> 4) << 3) + (lane & 7);
    int bKb  = ((lane >> 3) & 1) << 4;

    for (int c = 0; c < nChunks; c++) {
        CP_WAIT1();
        __syncthreads();

        uint32_t pA = sbase + (c & 1) * BUF_BYTES;
        uint32_t pB = pA + TILE_A;

        int rem = K - c * 64;
        int ksteps = rem >= 64 ? 4 : (rem + 15) >> 4;
        for (int ks = 0; ks < ksteps; ks++) {
            int kbyte = ks * 32;
            uint32_t af[2][4], bf[2][4];
#pragma unroll
            for (int mt = 0; mt < 2; mt++) {
                int off = (aRow + mt * 16) * 128 + kbyte + aKb;
                ldsm4(af[mt], pA + SWZ128(off));
            }
#pragma unroll
            for (int p = 0; p < 2; p++) {
                int off = (bRowP + p * 16) * 128 + kbyte + bKb;
                ldsm4(bf[p], pB + SWZ128(off));
            }
#pragma unroll
            for (int mt = 0; mt < 2; mt++)
#pragma unroll
                for (int p = 0; p < 2; p++) {
                    mma16816(acc[mt][2 * p],     af[mt], bf[p]);
                    mma16816(acc[mt][2 * p + 1], af[mt], bf[p] + 2);
                }
        }
        __syncthreads();
        if (c + 2 < nChunks) {
            issue(c + 2, c & 1);
        }
        CP_COMMIT();
    }

    // ---------------- epilogue ----------------
#pragma unroll
    for (int mt = 0; mt < 2; mt++) {
        int r0 = rowBase + wm * 32 + mt * 16 + (lane >> 2);
#pragma unroll
        for (int half = 0; half < 2; half++) {
            int row = r0 + half * 8;
            if (row >= M) continue;
            int trow = 0;
            if (EPI == 2) {
                int n = row / (Wcfg * Lw);
                int rem2 = row - n * (Wcfg * Lw);
                int w = rem2 / Lw, l = rem2 - w * Lw;
                trow = (n * Tcfg + w + l) * Dcfg;
            }
#pragma unroll
            for (int nt = 0; nt < 4; nt++) {
                int col = colBase + wn * 32 + nt * 8 + ((lane & 3) << 1);
                if (col >= Nn) continue;
                float v0 = acc[mt][nt][half * 2 + 0] + bias[col];
                float v1 = acc[mt][nt][half * 2 + 1] + bias[col + 1];
                if (EPI == 1 || EPI == 4) {
                    if (EPI == 1) {
                        v0 = 0.5f * v0 * (1.f + erff(v0 * 0.70710678118654752440f));
                        v1 = 0.5f * v1 * (1.f + erff(v1 * 0.70710678118654752440f));
                    }
                    size_t o = (size_t)row * Nn + col;
                    *(__half2*)(Ch + o) = __floats2half2_rn(v0, v1);
                } else {
                    if (EPI == 2) { v0 += res[trow + col]; v1 += res[trow + col + 1]; }
                    if (EPI == 3) {
                        size_t o = (size_t)row * Nn + col;
                        v0 += res[o]; v1 += res[o + 1];
                    }
                    *(float2*)(Cf + (size_t)row * Nn + col) = make_float2(v0, v1);
                }
            }
        }
    }
}

// ---------------- kernel: [N,C,T,V] -> [N,T,D] + PE, emit fp32 + fp16 --------------
__global__ void k_build_xs(const float* __restrict__ x, const float* __restrict__ pe) {
    int idx = blockIdx.x * 256 + threadIdx.x;
    if (idx >= NT * Dcfg) return;
    int d   = idx % Dcfg;
    int row = idx / Dcfg;
    int t = row % Tcfg, n = row / Tcfg;
    int v = d / Ccfg,   c = d % Ccfg;
    float val = x[((size_t)(n * Ccfg + c) * Tcfg + t) * Vcfg + v] + pe[t * Dcfg + d];
    g_xs[idx] = val;
    g_xs_f[idx] = __float2half(val);
}

// ---------------- fp32 -> fp16 conversion (vectorized; n % 4 == 0) -----------------
__global__ void k_tohalf(const float* __restrict__ src, hf* __restrict__ dst, int n4) {
    int i = blockIdx.x * 256 + threadIdx.x;
    if (i >= n4) return;
    float4 v = ((const float4*)src)[i];
    store_half4(dst + (size_t)i * 4, v);
}

// ---------------- attention: WB=3 windows per block, fp16 QKV in ---------------------
// block b: n = b/97, w0 = (b%97)*3; loads 11-token QKV span once.
__global__ void __launch_bounds__(256) k_attn() {
    __shared__ __align__(16) float sbuf[TOK * 3 * Dcfg];  // 11 x 1200 fp32 = 52.8 KB
    __shared__ float ssc[WB * 2 * 81];                    // 486 scores
    int b = blockIdx.x;
    int n = b / 97, w0 = (b - n * 97) * WB;
    int tid = threadIdx.x;

    // load 11 x 1200 halves (contiguous) -> fp32 smem; 1650 uint4 (8 halves each)
    {
        const uint4* src = (const uint4*)(g_qkv_f + (size_t)(n * Tcfg + w0) * 1200);
        float4* s4 = (float4*)sbuf;
        for (int idx = tid; idx < TOK * 150; idx += 256) {
            uint4 u = src[idx];
            __half2* hp = (__half2*)&u;
            float2 f0 = __half22float2(hp[0]);
            float2 f1 = __half22float2(hp[1]);
            float2 f2 = __half22float2(hp[2]);
            float2 f3 = __half22float2(hp[3]);
            s4[idx * 2 + 0] = make_float4(f0.x, f0.y, f1.x, f1.y);
            s4[idx * 2 + 1] = make_float4(f2.x, f2.y, f3.x, f3.y);
        }
    }
    __syncthreads();

    int wid = tid >> 5, lane = tid & 31;
    // scores: p = win*162 + h*81 + i*9 + j
    for (int p = wid; p < WB * 162; p += 8) {
        int win = p / 162, rem = p - win * 162;
        int h = rem / 81, r2 = rem - h * 81;
        int i = r2 / 9, j = r2 - i * 9;
        const float4* qp = (const float4*)&sbuf[(win + i) * 1200 + h * DH];
        const float4* kp = (const float4*)&sbuf[(win + j) * 1200 + Dcfg + h * DH];
        float s = 0.f;
        for (int d4 = lane; d4 < DH / 4; d4 += 32) {
            float4 qv = qp[d4], kv = kp[d4];
            s += qv.x * kv.x + qv.y * kv.y + qv.z * kv.z + qv.w * kv.w;
        }
#pragma unroll
        for (int o = 16; o; o >>= 1) s += __shfl_xor_sync(0xffffffffu, s, o);
        if (lane == 0) ssc[p] = s * 0.07071067811865475f;   // 1/sqrt(200)
    }
    __syncthreads();

    if (tid < WB * 18) {                     // softmax row (win, h, i)
        int win = tid / 18, rh = tid - win * 18;
        float* r = &ssc[win * 162 + (rh / 9) * 81 + (rh % 9) * 9];
        float m = r[0];
#pragma unroll
        for (int j = 1; j < 9; j++) m = fmaxf(m, r[j]);
        float s = 0.f;
#pragma unroll
        for (int j = 0; j < 9; j++) { float e = expf(r[j] - m); r[j] = e; s += e; }
        float inv = 1.f / s;
#pragma unroll
        for (int j = 0; j < 9; j++) r[j] *= inv;
    }
    __syncthreads();

    // AV: WB*9 rows x 100 float4
    const float4* s4 = (const float4*)sbuf;
    for (int idx = tid; idx < WB * 900; idx += 256) {
        int win = idx / 900, r = idx - win * 900;
        int i = r / 100, c4 = r - i * 100;
        int h = (c4 >= 50);
        const float* att = &ssc[win * 162 + h * 81 + i * 9];
        float4 acc = make_float4(0.f, 0.f, 0.f, 0.f);
#pragma unroll
        for (int j = 0; j < 9; j++) {
            float aj = att[j];
            float4 vv = s4[(win + j) * 300 + 200 + c4];
            acc.x += aj * vv.x; acc.y += aj * vv.y;
            acc.z += aj * vv.z; acc.w += aj * vv.w;
        }
        size_t orow = ((size_t)(n * Wcfg + w0 + win) * Lw + i) * Dcfg;
        store_half4(&g_attn_f[orow + c4 * 4], acc);
    }
}

// ---------------- layernorm over rows of 400, in place; optional fp16 plane --------
__global__ void __launch_bounds__(128) k_ln(float* __restrict__ X,
                                            const float* __restrict__ g,
                                            const float* __restrict__ bb,
                                            hf* __restrict__ out16) {
    int row = blockIdx.x;
    float4* xr4 = (float4*)(X + (size_t)row * Dcfg);
    int tid = threadIdx.x;
    float4 v4 = make_float4(0.f, 0.f, 0.f, 0.f);
    float s = 0.f, s2 = 0.f;
    if (tid < 100) {
        v4 = xr4[tid];
        s  = v4.x + v4.y + v4.z + v4.w;
        s2 = v4.x * v4.x + v4.y * v4.y + v4.z * v4.z + v4.w * v4.w;
    }
#pragma unroll
    for (int o = 16; o; o >>= 1) {
        s  += __shfl_xor_sync(0xffffffffu, s, o);
        s2 += __shfl_xor_sync(0xffffffffu, s2, o);
    }
    __shared__ float sh[10];
    int wid = tid >> 5, lane = tid & 31;
    if (lane == 0) { sh[wid] = s; sh[4 + wid] = s2; }
    __syncthreads();
    if (tid == 0) {
        float ts  = sh[0] + sh[1] + sh[2] + sh[3];
        float ts2 = sh[4] + sh[5] + sh[6] + sh[7];
        float mu  = ts * (1.f / Dcfg);
        float var = ts2 * (1.f / Dcfg) - mu * mu;
        sh[8] = mu; sh[9] = rsqrtf(var + 1e-5f);
    }
    __syncthreads();
    float mu = sh[8], rstd = sh[9];
    if (tid < 100) {
        float4 g4 = ((const float4*)g)[tid];
        float4 b4 = ((const float4*)bb)[tid];
        float4 r;
        r.x = (v4.x - mu) * rstd * g4.x + b4.x;
        r.y = (v4.y - mu) * rstd * g4.y + b4.y;
        r.z = (v4.z - mu) * rstd * g4.z + b4.z;
        r.w = (v4.w - mu) * rstd * g4.w + b4.w;
        xr4[tid] = r;
        if (out16) store_half4(out16 + (size_t)row * Dcfg + tid * 4, r);
    }
}

// ---------------- overlap-add gather + output permute [N,T,D]->[N,C,T,V], f4 -------
__global__ void k_gather(float* __restrict__ out) {
    int idx = blockIdx.x * 256 + threadIdx.x;
    if (idx >= NT * 100) return;               // float4 granules
    int d4 = idx % 100;
    int r = idx / 100;
    int t = r % Tcfg, n = r / Tcfg;
    float4 acc = make_float4(0.f, 0.f, 0.f, 0.f);
    int lmax = t < 8 ? t : 8;
    for (int l = 0; l <= lmax; l++) {
        int w0 = 2 * (t - l);
        if (w0 < Wcfg) {
            const float4* p0 = (const float4*)&g_h2[((size_t)((n * Wcfg + w0) * Lw + l)) * Dcfg];
            float4 a = p0[d4];
            acc.x += a.x; acc.y += a.y; acc.z += a.z; acc.w += a.w;
            if (w0 + 1 < Wcfg) {
                const float4* p1 = (const float4*)&g_h2[((size_t)((n * Wcfg + w0 + 1) * Lw + l)) * Dcfg];
                float4 bq = p1[d4];
                acc.x += bq.x; acc.y += bq.y; acc.z += bq.z; acc.w += bq.w;
            }
        }
    }
    int d = d4 * 4;
    int v = d / Ccfg, c0 = d % Ccfg;
    float vals[4] = {acc.x, acc.y, acc.z, acc.w};
#pragma unroll
    for (int j = 0; j < 4; j++)
        out[((size_t)(n * Ccfg + c0 + j) * Tcfg + t) * Vcfg + v] = vals[j];
}

// ---------------- launch ----------------
extern "C" void kernel_launch(void* const* d_in, const int* in_sizes, int n_in,
                              void* d_out, int out_size) {
    (void)in_sizes; (void)n_in; (void)out_size;
    const float* x     = (const float*)d_in[0];
    const float* pe    = (const float*)d_in[1];
    const float* w_in  = (const float*)d_in[2];
    const float* b_in  = (const float*)d_in[3];
    const float* w_out = (const float*)d_in[4];
    const float* b_out = (const float*)d_in[5];
    const float* w1    = (const float*)d_in[6];
    const float* b1    = (const float*)d_in[7];
    const float* w2    = (const float*)d_in[8];
    const float* b2    = (const float*)d_in[9];
    const float* ln1g  = (const float*)d_in[10];
    const float* ln1b  = (const float*)d_in[11];
    const float* ln2g  = (const float*)d_in[12];
    const float* ln2b  = (const float*)d_in[13];
    float* out = (float*)d_out;

    float *xs, *h1, *h2;
    hf *xsf, *winf, *woutf, *w1f, *w2f, *qkvf, *attf, *h1f, *fff;
    cudaGetSymbolAddress((void**)&xs,    g_xs);
    cudaGetSymbolAddress((void**)&h1,    g_h1);
    cudaGetSymbolAddress((void**)&h2,    g_h2);
    cudaGetSymbolAddress((void**)&xsf,   g_xs_f);
    cudaGetSymbolAddress((void**)&winf,  g_win_f);
    cudaGetSymbolAddress((void**)&woutf, g_wout_f);
    cudaGetSymbolAddress((void**)&w1f,   g_w1_f);
    cudaGetSymbolAddress((void**)&w2f,   g_w2_f);
    cudaGetSymbolAddress((void**)&qkvf,  g_qkv_f);
    cudaGetSymbolAddress((void**)&attf,  g_attn_f);
    cudaGetSymbolAddress((void**)&h1f,   g_h1_f);
    cudaGetSymbolAddress((void**)&fff,   g_ff_f);

    cudaFuncSetAttribute(k_mma<1>, cudaFuncAttributeMaxDynamicSharedMemorySize, SMEM_TOTAL);
    cudaFuncSetAttribute(k_mma<2>, cudaFuncAttributeMaxDynamicSharedMemorySize, SMEM_TOTAL);
    cudaFuncSetAttribute(k_mma<3>, cudaFuncAttributeMaxDynamicSharedMemorySize, SMEM_TOTAL);
    cudaFuncSetAttribute(k_mma<4>, cudaFuncAttributeMaxDynamicSharedMemorySize, SMEM_TOTAL);

    // 1. permute + PE (+ fp16)
    k_build_xs<<<(NT * Dcfg + 255) / 256, 256>>>(x, pe);

    // weight conversions (vectorized)
    k_tohalf<<<(3 * Dcfg * Dcfg / 4 + 255) / 256, 256>>>(w_in,  winf,  3 * Dcfg * Dcfg / 4);
    k_tohalf<<<(Dcfg * Dcfg / 4 + 255) / 256, 256>>>(w_out, woutf, Dcfg * Dcfg / 4);
    k_tohalf<<<(FFc * Dcfg / 4 + 255) / 256, 256>>>(w1, w1f, FFc * Dcfg / 4);
    k_tohalf<<<(Dcfg * FFc / 4 + 255) / 256, 256>>>(w2, w2f, Dcfg * FFc / 4);

    // 2. per-token QKV: [4800,400] @ [1200,400]^T -> fp16
    {
        dim3 g((3 * Dcfg + 63) / 64, (NT + 127) / 128);
        k_mma<4><<<g, 256, SMEM_TOTAL>>>(xsf, winf, b_in, nullptr,
                                         nullptr, qkvf, NT, 3 * Dcfg, Dcfg);
    }

    // 3. windowed attention (3 windows/block) -> fp16 plane
    k_attn<<<Ncfg * 97, 256>>>();

    // 4. out-proj + residual (gathered xs) -> h1 fp32, then LN1 (+ fp16)
    {
        dim3 g((Dcfg + 63) / 64, (M2 + 127) / 128);
        k_mma<2><<<g, 256, SMEM_TOTAL>>>(attf, woutf, b_out, xs,
                                         h1, nullptr, M2, Dcfg, Dcfg);
    }
    k_ln<<<M2, 128>>>(h1, ln1g, ln1b, h1f);

    // 5. FFN up + gelu -> ff fp16
    {
        dim3 g((FFc + 63) / 64, (M2 + 127) / 128);
        k_mma<1><<<g, 256, SMEM_TOTAL>>>(h1f, w1f, b1, nullptr,
                                         nullptr, fff, M2, FFc, Dcfg);
    }
    // 6. FFN down + residual -> h2 fp32, then LN2
    {
        dim3 g((Dcfg + 63) / 64, (M2 + 127) / 128);
        k_mma<3><<<g, 256, SMEM_TOTAL>>>(fff, w2f, b2, h1,
                                         h2, nullptr, M2, Dcfg, FFc);
    }
    k_ln<<<M2, 128>>>(h2, ln2g, ln2b, nullptr);

    // 7. overlap-add gather + output permute
    k_gather<<<(NT * 100 + 255) / 256, 256>>>(out);
}